// round 3
// baseline (speedup 1.0000x reference)
#include <cuda_runtime.h>

#define NN 10000
#define EE 640000
#define C  128
#define C4 (C/4)
#define NB 16   // nodes per block in the node-level GEMMs

// Scratch (device globals; float4 => guaranteed 16B alignment)
__device__ float4 g_A[NN * C4];   // x @ W1[:128]   (sender path, pre-edge_attr)
__device__ float4 g_B[NN * C4];   // x @ W1[128:]   (receiver path)
__device__ float4 g_H[NN * C4];   // sum of relu'd hidden vectors per receiver
__device__ float  g_deg[NN];      // in-degree per node (as float)

// ---------------------------------------------------------------------------
// Kernel 1: A = x @ W1a, B = x @ W1b. Also zeroes H and deg for this launch.
// Block = 128 threads (one per output channel), NB nodes per block.
// ---------------------------------------------------------------------------
__global__ __launch_bounds__(128) void ab_kernel(const float* __restrict__ x,
                                                 const float* __restrict__ W1) {
    // zero scratch accumulators (grid-stride)
    int gt = blockIdx.x * 128 + threadIdx.x;
    int total = gridDim.x * 128;
    float4 z = make_float4(0.f, 0.f, 0.f, 0.f);
    for (int i = gt; i < NN * C4; i += total) g_H[i] = z;
    for (int i = gt; i < NN;      i += total) g_deg[i] = 0.f;

    __shared__ float sx[NB][C];
    int n0 = blockIdx.x * NB;
    int tid = threadIdx.x;
    for (int i = tid; i < NB * C; i += 128)
        sx[i / C][i % C] = x[n0 * C + i];
    __syncthreads();

    int c = tid;
    float accA[NB], accB[NB];
#pragma unroll
    for (int n = 0; n < NB; n++) { accA[n] = 0.f; accB[n] = 0.f; }

    for (int k = 0; k < C; k++) {
        float wa = W1[k * C + c];          // W1 row k   (x_i half)
        float wb = W1[(k + C) * C + c];    // W1 row k+C (x_j half)
#pragma unroll
        for (int n = 0; n < NB; n++) {
            accA[n] = fmaf(sx[n][k], wa, accA[n]);
            accB[n] = fmaf(sx[n][k], wb, accB[n]);
        }
    }
    float* Af = (float*)g_A;
    float* Bf = (float*)g_B;
#pragma unroll
    for (int n = 0; n < NB; n++) {
        Af[(n0 + n) * C + c] = accA[n];
        Bf[(n0 + n) * C + c] = accB[n];
    }
}

// ---------------------------------------------------------------------------
// Kernel 2: per-edge hidden vector + scatter-add aggregation.
// One warp per edge; each lane owns 4 channels (float4).
//   h = relu(ea * A[row] + B[col] + b1);  H[col] += h;  deg[col] += 1
// edge_index is INT32 (JAX x64 disabled => int64 request degrades to int32).
// ---------------------------------------------------------------------------
__global__ __launch_bounds__(256) void edge_kernel(const int* __restrict__ ei,
                                                   const float* __restrict__ ea,
                                                   const float* __restrict__ b1) {
    int e    = (blockIdx.x * 256 + threadIdx.x) >> 5;
    int lane = threadIdx.x & 31;
    if (e >= EE) return;

    int   row = __ldg(ei + e);
    int   col = __ldg(ei + EE + e);
    float w   = __ldg(ea + e);

    const float4 a  = g_A[row * C4 + lane];
    const float4 b  = g_B[col * C4 + lane];
    const float4 bb = __ldg((const float4*)b1 + lane);

    float4 h;
    h.x = fmaxf(fmaf(w, a.x, b.x + bb.x), 0.f);
    h.y = fmaxf(fmaf(w, a.y, b.y + bb.y), 0.f);
    h.z = fmaxf(fmaf(w, a.z, b.z + bb.z), 0.f);
    h.w = fmaxf(fmaf(w, a.w, b.w + bb.w), 0.f);

    float* dst = (float*)(g_H + col * C4 + lane);
    atomicAdd(dst + 0, h.x);   // result unused -> REDG
    atomicAdd(dst + 1, h.y);
    atomicAdd(dst + 2, h.z);
    atomicAdd(dst + 3, h.w);
    if (lane == 0) atomicAdd(g_deg + col, 1.0f);
}

// ---------------------------------------------------------------------------
// Kernel 3: out = H @ W2 + deg * b2
// ---------------------------------------------------------------------------
__global__ __launch_bounds__(128) void out_kernel(const float* __restrict__ W2,
                                                  const float* __restrict__ b2,
                                                  float* __restrict__ out) {
    __shared__ float sh[NB][C];
    int n0 = blockIdx.x * NB;
    int tid = threadIdx.x;
    const float* Hf = (const float*)g_H;
    for (int i = tid; i < NB * C; i += 128)
        sh[i / C][i % C] = Hf[n0 * C + i];
    __syncthreads();

    int c = tid;
    float acc[NB];
#pragma unroll
    for (int n = 0; n < NB; n++) acc[n] = 0.f;

    for (int k = 0; k < C; k++) {
        float w = W2[k * C + c];
#pragma unroll
        for (int n = 0; n < NB; n++) acc[n] = fmaf(sh[n][k], w, acc[n]);
    }
    float bc = b2[c];
#pragma unroll
    for (int n = 0; n < NB; n++)
        out[(n0 + n) * C + c] = acc[n] + g_deg[n0 + n] * bc;
}

// ---------------------------------------------------------------------------
extern "C" void kernel_launch(void* const* d_in, const int* in_sizes, int n_in,
                              void* d_out, int out_size) {
    const float* x  = (const float*)d_in[0];   // [N, 128]
    const int*   ei = (const int*)d_in[1];     // [2, E] int32 (JAX default x64-off)
    const float* ea = (const float*)d_in[2];   // [E]
    const float* W1 = (const float*)d_in[3];   // [256, 128]
    const float* b1 = (const float*)d_in[4];   // [128]
    const float* W2 = (const float*)d_in[5];   // [128, 128]
    const float* b2 = (const float*)d_in[6];   // [128]
    float* out = (float*)d_out;                // [N, 128]

    ab_kernel<<<NN / NB, 128>>>(x, W1);
    edge_kernel<<<(EE * 32 + 255) / 256, 256>>>(ei, ea, b1);
    out_kernel<<<NN / NB, 128>>>(W2, b2, out);
}

// round 4
// speedup vs baseline: 1.9438x; 1.9438x over previous
#include <cuda_runtime.h>

#define NN 10000
#define EE 640000
#define C  128
#define C4 (C/4)
#define NB 8    // nodes per block in the node-level GEMMs

// Scratch (device globals; float4 => guaranteed 16B alignment)
__device__ float4 g_A[NN * C4];   // x @ W1[:128]   (sender path, pre-edge_attr)
__device__ float4 g_B[NN * C4];   // x @ W1[128:]   (receiver path)
__device__ float4 g_H[NN * C4];   // sum of relu'd hidden vectors per receiver
__device__ float  g_deg[NN];      // in-degree per node (as float)

// ---------------------------------------------------------------------------
// Kernel 1: A = x @ W1a, B = x @ W1b. Also zeroes H and deg for this launch.
// 256 threads: lower half computes A channels, upper half computes B channels.
// ---------------------------------------------------------------------------
__global__ __launch_bounds__(256) void ab_kernel(const float* __restrict__ x,
                                                 const float* __restrict__ W1) {
    // zero scratch accumulators (grid-stride)
    int gt = blockIdx.x * 256 + threadIdx.x;
    int total = gridDim.x * 256;
    float4 z = make_float4(0.f, 0.f, 0.f, 0.f);
    for (int i = gt; i < NN * C4; i += total) g_H[i] = z;
    for (int i = gt; i < NN;      i += total) g_deg[i] = 0.f;

    __shared__ float sx[NB][C];
    int n0 = blockIdx.x * NB;
    int tid = threadIdx.x;
    for (int i = tid; i < NB * C; i += 256)
        sx[i / C][i % C] = x[n0 * C + i];
    __syncthreads();

    int half = tid >> 7;                   // 0 -> A (W1 rows 0..127), 1 -> B (rows 128..255)
    int c    = tid & 127;
    const float* Wb = W1 + half * C * C;

    float acc[NB];
#pragma unroll
    for (int n = 0; n < NB; n++) acc[n] = 0.f;

    for (int k = 0; k < C; k++) {
        float w = Wb[k * C + c];
#pragma unroll
        for (int n = 0; n < NB; n++) acc[n] = fmaf(sx[n][k], w, acc[n]);
    }
    float* Of = half ? (float*)g_B : (float*)g_A;
#pragma unroll
    for (int n = 0; n < NB; n++)
        Of[(n0 + n) * C + c] = acc[n];
}

// ---------------------------------------------------------------------------
// Kernel 2: per-edge hidden vector + scatter-add aggregation.
// One warp per edge; each lane owns 4 channels (float4).
//   h = relu(ea * A[row] + B[col] + b1);  H[col] += h (red.v4);  deg[col] += 1
// ---------------------------------------------------------------------------
__global__ __launch_bounds__(256) void edge_kernel(const int* __restrict__ ei,
                                                   const float* __restrict__ ea,
                                                   const float* __restrict__ b1) {
    int e    = (blockIdx.x * 256 + threadIdx.x) >> 5;
    int lane = threadIdx.x & 31;
    if (e >= EE) return;

    int   row = __ldg(ei + e);
    int   col = __ldg(ei + EE + e);
    float w   = __ldg(ea + e);

    const float4 a  = g_A[row * C4 + lane];
    const float4 b  = g_B[col * C4 + lane];
    const float4 bb = __ldg((const float4*)b1 + lane);

    float4 h;
    h.x = fmaxf(fmaf(w, a.x, b.x + bb.x), 0.f);
    h.y = fmaxf(fmaf(w, a.y, b.y + bb.y), 0.f);
    h.z = fmaxf(fmaf(w, a.z, b.z + bb.z), 0.f);
    h.w = fmaxf(fmaf(w, a.w, b.w + bb.w), 0.f);

    // Single vector reduction: 1 L2 atomic op per 16B instead of 4 per 4B.
    float4* dst = g_H + col * C4 + lane;
    asm volatile("red.global.add.v4.f32 [%0], {%1, %2, %3, %4};"
                 :: "l"(dst), "f"(h.x), "f"(h.y), "f"(h.z), "f"(h.w)
                 : "memory");

    if (lane == 0) atomicAdd(g_deg + col, 1.0f);
}

// ---------------------------------------------------------------------------
// Kernel 3: out = H @ W2 + deg * b2
// ---------------------------------------------------------------------------
__global__ __launch_bounds__(128) void out_kernel(const float* __restrict__ W2,
                                                  const float* __restrict__ b2,
                                                  float* __restrict__ out) {
    __shared__ float sh[NB][C];
    int n0 = blockIdx.x * NB;
    int tid = threadIdx.x;
    const float* Hf = (const float*)g_H;
    for (int i = tid; i < NB * C; i += 128)
        sh[i / C][i % C] = Hf[n0 * C + i];
    __syncthreads();

    int c = tid;
    float acc[NB];
#pragma unroll
    for (int n = 0; n < NB; n++) acc[n] = 0.f;

    for (int k = 0; k < C; k++) {
        float w = W2[k * C + c];
#pragma unroll
        for (int n = 0; n < NB; n++) acc[n] = fmaf(sh[n][k], w, acc[n]);
    }
    float bc = b2[c];
#pragma unroll
    for (int n = 0; n < NB; n++)
        out[(n0 + n) * C + c] = acc[n] + g_deg[n0 + n] * bc;
}

// ---------------------------------------------------------------------------
extern "C" void kernel_launch(void* const* d_in, const int* in_sizes, int n_in,
                              void* d_out, int out_size) {
    const float* x  = (const float*)d_in[0];   // [N, 128]
    const int*   ei = (const int*)d_in[1];     // [2, E] int32
    const float* ea = (const float*)d_in[2];   // [E]
    const float* W1 = (const float*)d_in[3];   // [256, 128]
    const float* b1 = (const float*)d_in[4];   // [128]
    const float* W2 = (const float*)d_in[5];   // [128, 128]
    const float* b2 = (const float*)d_in[6];   // [128]
    float* out = (float*)d_out;                // [N, 128]

    ab_kernel<<<NN / NB, 256>>>(x, W1);
    edge_kernel<<<(EE * 32 + 255) / 256, 256>>>(ei, ea, b1);
    out_kernel<<<NN / NB, 128>>>(W2, b2, out);
}